// round 3
// baseline (speedup 1.0000x reference)
#include <cuda_runtime.h>
#include <cuda_bf16.h>

// FixedTagLoss: weighted cross-entropy over [B=2, S=4096, V=32000] fp32 logits.
// HBM-bound: single streaming read of logits (1.05 GB).
// Labels are int32 (JAX demotes int64 without x64 flag).
// Per-thread ONLINE softmax (running max + rescaled sum) keeps register count
// low (~40) so 3 CTAs/SM overlap exp phases with other CTAs' memory phases.

#define BB   2
#define SS   4096
#define VV   32000
#define ROWS (BB * SS)            // 8192
#define TPB  512
#define V4   (VV / 4)             // 8000 float4 per row
#define FULL_IT (V4 / TPB)        // 15 full float4 per thread
#define TAIL (V4 - FULL_IT * TPB) // 320 leftover float4 (threads 0..319)

__device__ float g_wnll[ROWS];
__device__ float g_w[ROWS];

__device__ __forceinline__ void online_upd(float x, float& m, float& s)
{
    if (x > m) { s *= __expf(m - x); m = x; }   // rare: running-max record
    s += __expf(x - m);
}

__device__ __forceinline__ void upd4(float4 a, float& m, float& s)
{
    online_upd(a.x, m, s);
    online_upd(a.y, m, s);
    online_upd(a.z, m, s);
    online_upd(a.w, m, s);
}

__global__ __launch_bounds__(TPB)
void row_lse_kernel(const float* __restrict__ logits,
                    const int* __restrict__ labels)
{
    const int row = blockIdx.x;
    const int tid = threadIdx.x;
    const float4* rp = reinterpret_cast<const float4*>(logits + (size_t)row * VV);

    float m = -3.402823e38f;
    float s = 0.0f;

    // ---- stream 15 float4 per thread in batches of 5 (MLP >= 5) ----
#pragma unroll
    for (int k = 0; k < FULL_IT; k += 5) {
        float4 a0 = rp[tid + (k + 0) * TPB];
        float4 a1 = rp[tid + (k + 1) * TPB];
        float4 a2 = rp[tid + (k + 2) * TPB];
        float4 a3 = rp[tid + (k + 3) * TPB];
        float4 a4 = rp[tid + (k + 4) * TPB];
        upd4(a0, m, s);
        upd4(a1, m, s);
        upd4(a2, m, s);
        upd4(a3, m, s);
        upd4(a4, m, s);
    }
    if (tid < TAIL) {
        float4 at = rp[FULL_IT * TPB + tid];
        upd4(at, m, s);
    }

    // ---- deterministic block combine of (m, s) pairs via smem tree ----
    __shared__ float sm[TPB];
    __shared__ float ss[TPB];
    sm[tid] = m;
    ss[tid] = s;
    __syncthreads();
#pragma unroll
    for (int off = TPB / 2; off > 0; off >>= 1) {
        if (tid < off) {
            const float m1 = sm[tid],       s1 = ss[tid];
            const float m2 = sm[tid + off], s2 = ss[tid + off];
            const float M  = fmaxf(m1, m2);
            sm[tid] = M;
            ss[tid] = s1 * __expf(m1 - M) + s2 * __expf(m2 - M);
        }
        __syncthreads();
    }

    // ---- thread 0: nll, tag-coverage weight, store per-row result ----
    if (tid == 0) {
        const float lse = sm[0] + __logf(ss[0]);
        int lab = labels[row];
        if (lab < 0)   lab = 0;         // defensive clamp (should never hit)
        if (lab >= VV) lab = VV - 1;
        const float xl = logits[(size_t)row * VV + lab];  // L2 hit
        const float nll = lse - xl;

        const int b  = row / SS;
        const int sp = row % SS;
        const int* L = labels + (size_t)b * SS;
        bool cov = false;
        // tag (11, 22, 33): sp covered if a match starts at sp-k, k in [0,3)
#pragma unroll
        for (int k = 0; k < 3; k++) {
            const int st = sp - k;
            if (st >= 0 && st + 3 <= SS) {
                if (L[st] == 11 && L[st + 1] == 22 && L[st + 2] == 33) cov = true;
            }
        }
        // tag (44, 55)
#pragma unroll
        for (int k = 0; k < 2; k++) {
            const int st = sp - k;
            if (st >= 0 && st + 2 <= SS) {
                if (L[st] == 44 && L[st + 1] == 55) cov = true;
            }
        }
        const float w = cov ? 2.0f : 1.0f;
        g_w[row]    = w;
        g_wnll[row] = w * nll;
    }
}

__global__ __launch_bounds__(1024)
void final_reduce_kernel(float* __restrict__ out)
{
    const int tid = threadIdx.x;
    float num = 0.0f, den = 0.0f;
#pragma unroll
    for (int k = 0; k < ROWS / 1024; k++) {   // 8 per thread, fixed order
        num += g_wnll[tid + k * 1024];
        den += g_w[tid + k * 1024];
    }
    __shared__ float sn[1024];
    __shared__ float sd[1024];
    sn[tid] = num;
    sd[tid] = den;
    __syncthreads();
#pragma unroll
    for (int off = 512; off > 0; off >>= 1) {
        if (tid < off) {
            sn[tid] += sn[tid + off];
            sd[tid] += sd[tid + off];
        }
        __syncthreads();
    }
    if (tid == 0) out[0] = sn[0] / sd[0];
}

extern "C" void kernel_launch(void* const* d_in, const int* in_sizes, int n_in,
                              void* d_out, int out_size)
{
    const float* logits = (const float*)d_in[0];
    const int*   labels = (const int*)d_in[1];

    row_lse_kernel<<<ROWS, TPB>>>(logits, labels);
    final_reduce_kernel<<<1, 1024>>>((float*)d_out);
}

// round 8
// speedup vs baseline: 1.0427x; 1.0427x over previous
#include <cuda_runtime.h>
#include <cuda_bf16.h>
#include <float.h>

// FixedTagLoss: weighted cross-entropy over [B=2, S=4096, V=32000] fp32 logits.
// Single fused kernel: HBM-bound streaming read (1.05 GB), per-thread batched
// softmax (per-batch max + independent exps over 4 accumulators), warp-shuffle
// block combine, and last-CTA final reduction (threadfence-reduction pattern;
// fixed summation order -> bitwise deterministic output).

#define BB   2
#define SS   4096
#define VV   32000
#define ROWS (BB * SS)            // 8192
#define TPB  512
#define WARPS (TPB / 32)          // 16
#define V4   (VV / 4)             // 8000 float4 per row
#define FULL_IT (V4 / TPB)        // 15 full float4 per thread
#define TAIL (V4 - FULL_IT * TPB) // 320 leftover float4 (threads 0..319)

__device__ float g_wnll[ROWS];
__device__ float g_w[ROWS];
__device__ unsigned int g_count = 0;   // reset by last CTA each run

__device__ __forceinline__ float max4(float4 a)
{
    return fmaxf(fmaxf(a.x, a.y), fmaxf(a.z, a.w));
}

// Combine two (m, s) online-softmax states.
__device__ __forceinline__ void combine(float& m, float& s, float m2, float s2)
{
    const float M = fmaxf(m, m2);
    s = s * __expf(m - M) + s2 * __expf(m2 - M);
    m = M;
}

__global__ __launch_bounds__(TPB)
void fused_loss_kernel(const float* __restrict__ logits,
                       const int* __restrict__ labels,
                       float* __restrict__ out)
{
    const int row = blockIdx.x;
    const int tid = threadIdx.x;
    const int wid = tid >> 5;
    const int lid = tid & 31;
    const float4* rp = reinterpret_cast<const float4*>(logits + (size_t)row * VV);

    float m = -FLT_MAX;
    float s = 0.0f;

    // ---- stream 15 float4 per thread in batches of 5 (MLP >= 5), evict-first.
    //      Per batch: tree max (FMNMX), one rescale, 20 independent exps over
    //      4 accumulators (pipelined MUFU, no serial FADD chain, no divergence).
#pragma unroll
    for (int k = 0; k < FULL_IT; k += 5) {
        const float4 a0 = __ldcs(&rp[tid + (k + 0) * TPB]);
        const float4 a1 = __ldcs(&rp[tid + (k + 1) * TPB]);
        const float4 a2 = __ldcs(&rp[tid + (k + 2) * TPB]);
        const float4 a3 = __ldcs(&rp[tid + (k + 3) * TPB]);
        const float4 a4 = __ldcs(&rp[tid + (k + 4) * TPB]);

        const float bm = fmaxf(fmaxf(fmaxf(max4(a0), max4(a1)),
                                     fmaxf(max4(a2), max4(a3))), max4(a4));
        const float M = fmaxf(m, bm);
        s *= __expf(m - M);          // rescale previous sum (exp(0)=1 if no change)
        m = M;

        float t0 = __expf(a0.x - M) + __expf(a1.x - M);
        float t1 = __expf(a0.y - M) + __expf(a1.y - M);
        float t2 = __expf(a0.z - M) + __expf(a1.z - M);
        float t3 = __expf(a0.w - M) + __expf(a1.w - M);
        t0 += __expf(a2.x - M) + __expf(a3.x - M);
        t1 += __expf(a2.y - M) + __expf(a3.y - M);
        t2 += __expf(a2.z - M) + __expf(a3.z - M);
        t3 += __expf(a2.w - M) + __expf(a3.w - M);
        t0 += __expf(a4.x - M);
        t1 += __expf(a4.y - M);
        t2 += __expf(a4.z - M);
        t3 += __expf(a4.w - M);
        s += (t0 + t1) + (t2 + t3);
    }
    if (tid < TAIL) {
        const float4 at = __ldcs(&rp[FULL_IT * TPB + tid]);
        const float M = fmaxf(m, max4(at));
        s *= __expf(m - M);
        m = M;
        s += (__expf(at.x - M) + __expf(at.y - M))
           + (__expf(at.z - M) + __expf(at.w - M));
    }

    // ---- intra-warp shuffle combine (deterministic, 5 steps) ----
#pragma unroll
    for (int off = 16; off > 0; off >>= 1) {
        const float m2 = __shfl_down_sync(0xFFFFFFFFu, m, off);
        const float s2 = __shfl_down_sync(0xFFFFFFFFu, s, off);
        combine(m, s, m2, s2);
    }

    // ---- cross-warp combine via smem partials (1 barrier) ----
    __shared__ float smM[WARPS];
    __shared__ float smS[WARPS];
    __shared__ int   s_last;
    if (lid == 0) { smM[wid] = m; smS[wid] = s; }
    __syncthreads();

    if (wid == 0) {
        float mm = (lid < WARPS) ? smM[lid] : -FLT_MAX;
        float sv = (lid < WARPS) ? smS[lid] : 0.0f;
#pragma unroll
        for (int off = 8; off > 0; off >>= 1) {
            const float m2 = __shfl_down_sync(0xFFFFFFFFu, mm, off);
            const float s2 = __shfl_down_sync(0xFFFFFFFFu, sv, off);
            combine(mm, sv, m2, s2);
        }

        if (lid == 0) {
            const float lse = mm + __logf(sv);
            int lab = labels[row];
            if (lab < 0)   lab = 0;         // defensive clamp
            if (lab >= VV) lab = VV - 1;
            const float xl = logits[(size_t)row * VV + lab];  // L2 hit
            const float nll = lse - xl;

            const int b  = row / SS;
            const int sp = row % SS;
            const int* L = labels + (size_t)b * SS;
            bool cov = false;
            // tag (11, 22, 33): sp covered if a match starts at sp-k, k in [0,3)
#pragma unroll
            for (int k = 0; k < 3; k++) {
                const int st = sp - k;
                if (st >= 0 && st + 3 <= SS) {
                    if (L[st] == 11 && L[st + 1] == 22 && L[st + 2] == 33) cov = true;
                }
            }
            // tag (44, 55)
#pragma unroll
            for (int k = 0; k < 2; k++) {
                const int st = sp - k;
                if (st >= 0 && st + 2 <= SS) {
                    if (L[st] == 44 && L[st + 1] == 55) cov = true;
                }
            }
            const float w = cov ? 2.0f : 1.0f;
            g_w[row]    = w;
            g_wnll[row] = w * nll;

            __threadfence();
            const unsigned prev = atomicAdd(&g_count, 1u);
            s_last = (prev == ROWS - 1) ? 1 : 0;
        }
    }
    __syncthreads();

    // ---- last CTA: deterministic final reduce of all per-row results ----
    if (s_last) {
        float num = 0.0f, den = 0.0f;
#pragma unroll
        for (int k = 0; k < ROWS / TPB; k++) {   // 16 per thread, fixed order
            const int i = tid + k * TPB;
            num += __ldcg(&g_wnll[i]);
            den += __ldcg(&g_w[i]);
        }
#pragma unroll
        for (int off = 16; off > 0; off >>= 1) {
            num += __shfl_down_sync(0xFFFFFFFFu, num, off);
            den += __shfl_down_sync(0xFFFFFFFFu, den, off);
        }
        __shared__ float sn[WARPS];
        __shared__ float sd[WARPS];
        if (lid == 0) { sn[wid] = num; sd[wid] = den; }
        __syncthreads();
        if (wid == 0) {
            float n2 = (lid < WARPS) ? sn[lid] : 0.0f;
            float d2 = (lid < WARPS) ? sd[lid] : 0.0f;
#pragma unroll
            for (int off = 8; off > 0; off >>= 1) {
                n2 += __shfl_down_sync(0xFFFFFFFFu, n2, off);
                d2 += __shfl_down_sync(0xFFFFFFFFu, d2, off);
            }
            if (lid == 0) {
                out[0] = n2 / d2;
                g_count = 0;               // reset for next graph replay
            }
        }
    }
}

extern "C" void kernel_launch(void* const* d_in, const int* in_sizes, int n_in,
                              void* d_out, int out_size)
{
    const float* logits = (const float*)d_in[0];
    const int*   labels = (const int*)d_in[1];

    fused_loss_kernel<<<ROWS, TPB>>>(logits, labels, (float*)d_out);
}